// round 9
// baseline (speedup 1.0000x reference)
#include <cuda_runtime.h>
#include <stdint.h>

// Problem constants
#define BZ   32
#define SEQ  2048
#define D    768
#define P    16
#define PLACEHOLDER_ID 1
#define ROWS (BZ * SEQ)          // 65536
#define D4   (D / 4)             // 192 float4 per row
#define ROWB 3072                // bytes per row

#define GTPB 192
#define RPB  8
#define GBLOCKS (ROWS / RPB)     // 8192
#define TILEB (RPB * ROWB)       // 24576 B staged per block

__device__ __forceinline__ uint32_t smem_u32(const void* p) {
    uint32_t a;
    asm("{ .reg .u64 t; cvta.to.shared.u64 t, %1; cvt.u32.u64 %0, t; }"
        : "=r"(a) : "l"(p));
    return a;
}

// ---------------------------------------------------------------------------
// Single fused kernel. Block handles 8 consecutive rows of one batch row:
//   1) gather 8 emb rows into registers (8 independent LDG.128, MLP=8)
//   2) rare path (~494/8192 blocks): replace placeholder rows' register data
//      with prompt[rank] (rank recovered by cooperative count)
//   3) stage the finished 24KB tile in SMEM
//   4) emit ONE contiguous 24KB cp.async.bulk store -> long DRAM write bursts
//      instead of fine-grained interleaved STG.128 sectors.
// ---------------------------------------------------------------------------
__global__ __launch_bounds__(GTPB)
void fused_prompt_embed_kernel(const int* __restrict__ input_ids,
                               const float4* __restrict__ emb,
                               const float4* __restrict__ prompt,
                               float4* __restrict__ out) {
    __shared__ float4 stage[RPB * D4];       // 24576 bytes

    const int r0    = blockIdx.x * RPB;
    const int t     = threadIdx.x;
    const int batch = r0 >> 11;              // r0 / SEQ
    const int seq0  = r0 & (SEQ - 1);
    const int* rid  = input_ids + ((size_t)batch << 11);

    // 8 consecutive ids as two 16B loads (uniform per block)
    int4 ia = __ldg((const int4*)(rid + seq0));
    int4 ib = __ldg((const int4*)(rid + seq0) + 1);
    int ids[RPB] = { ia.x, ia.y, ia.z, ia.w, ib.x, ib.y, ib.z, ib.w };

    // 8 independent back-to-back gathers (PLACEHOLDER_ID=1 is a valid row)
    float4 v[RPB];
#pragma unroll
    for (int i = 0; i < RPB; i++)
        v[i] = __ldg(emb + (size_t)ids[i] * D4 + t);

    bool anyph = false;
#pragma unroll
    for (int i = 0; i < RPB; i++)
        anyph |= (ids[i] == PLACEHOLDER_ID);

    if (anyph) {                             // block-uniform rare path
        int cnt = 0;
        for (int j = t; j < seq0; j += GTPB)
            cnt += (__ldg(&rid[j]) == PLACEHOLDER_ID);

        __shared__ int s_sum;
        if (t == 0) s_sum = 0;
        __syncthreads();
#pragma unroll
        for (int off = 16; off > 0; off >>= 1)
            cnt += __shfl_down_sync(0xFFFFFFFFu, cnt, off);
        if ((t & 31) == 0) atomicAdd(&s_sum, cnt);
        __syncthreads();

        int rank = s_sum;                    // placeholders before seq0
#pragma unroll
        for (int i = 0; i < RPB; i++) {
            if (ids[i] == PLACEHOLDER_ID) {
                int r = rank < (P - 1) ? rank : (P - 1);
                v[i] = __ldg(&prompt[r * D4 + t]);
                rank++;
            }
        }
    }

    // Stage the complete tile in SMEM
#pragma unroll
    for (int i = 0; i < RPB; i++)
        stage[i * D4 + t] = v[i];

    // Order generic smem writes before the async-proxy bulk store
    asm volatile("fence.proxy.async.shared::cta;" ::: "memory");
    __syncthreads();

    // One contiguous 24KB bulk store (8 consecutive rows are contiguous in out)
    if (t == 0) {
        const float4* dst = out + (size_t)r0 * D4;
        asm volatile(
            "cp.async.bulk.global.shared::cta.bulk_group [%0], [%1], %2;\n\t"
            "cp.async.bulk.commit_group;\n\t"
            "cp.async.bulk.wait_group.read 0;"
            :: "l"(dst), "r"(smem_u32(stage)), "n"(TILEB)
            : "memory");
    }
}

// ---------------------------------------------------------------------------
extern "C" void kernel_launch(void* const* d_in, const int* in_sizes, int n_in,
                              void* d_out, int out_size) {
    const int*    input_ids = (const int*)d_in[0];
    const float4* emb       = (const float4*)d_in[1];
    const float4* prompt    = (const float4*)d_in[2];
    float4*       out       = (float4*)d_out;

    fused_prompt_embed_kernel<<<GBLOCKS, GTPB>>>(input_ids, emb, prompt, out);
}